// round 3
// baseline (speedup 1.0000x reference)
#include <cuda_runtime.h>

#define BN   4
#define NF   8
#define CC   8
#define NPIX (512 * 512)
#define NG   (NPIX / 4)
#define BLKX 148
#define TOTAL_BLOCKS (BLKX * BN)

struct Scratch {
    float sums[BN][CC][NF];   // 256
    float counts[BN][CC];     // 32
    float dist[BN];           // 4
    unsigned int arrive;
    unsigned int release;
    unsigned int ticket;
};
__device__ Scratch g_s;

__device__ __forceinline__ unsigned long long ffma2(unsigned long long a,
                                                    unsigned long long b,
                                                    unsigned long long c) {
    unsigned long long d;
    asm("fma.rn.f32x2 %0, %1, %2, %3;" : "=l"(d) : "l"(a), "l"(b), "l"(c));
    return d;
}
__device__ __forceinline__ unsigned long long fadd2(unsigned long long a,
                                                    unsigned long long b) {
    unsigned long long d;
    asm("add.rn.f32x2 %0, %1, %2;" : "=l"(d) : "l"(a), "l"(b));
    return d;
}
__device__ __forceinline__ unsigned long long pack2(float lo, float hi) {
    unsigned long long r;
    asm("mov.b64 %0, {%1, %2};" : "=l"(r) : "f"(lo), "f"(hi));
    return r;
}
__device__ __forceinline__ void unpack2(unsigned long long v, float& lo, float& hi) {
    asm("mov.b64 {%0, %1}, %2;" : "=f"(lo), "=f"(hi) : "l"(v));
}
__device__ __forceinline__ float f4get(const float4 v, int i) {
    return i == 0 ? v.x : i == 1 ? v.y : i == 2 ? v.z : v.w;
}
__device__ __forceinline__ int i4get(const int4 v, int i) {
    return i == 0 ? v.x : i == 1 ? v.y : i == 2 ? v.z : v.w;
}

__global__ void __launch_bounds__(128, 4)
k_fused(const float* __restrict__ pred, const int* __restrict__ tgt,
        float* __restrict__ out) {
    const int b   = blockIdx.y;
    const int tid = threadIdx.x;
    const float4* p = (const float4*)(pred + (size_t)b * NF * NPIX);
    const int4*   g = (const int4*)(tgt + (size_t)b * NPIX);
    const unsigned long long ONE2 = 0x3F8000003F800000ull;

    // ---------------- Phase A: per-cluster counts + feature sums -----------
    unsigned long long acc[CC][4];
    int icnt[CC];
#pragma unroll
    for (int c = 0; c < CC; c++) {
        icnt[c] = 0;
#pragma unroll
        for (int k = 0; k < 4; k++) acc[c][k] = 0ull;
    }

    for (int n = blockIdx.x * blockDim.x + tid; n < NG;
         n += BLKX * blockDim.x) {
        int4 lab4 = g[n];
        float4 v[NF];
#pragma unroll
        for (int f = 0; f < NF; f++) v[f] = p[f * (NPIX / 4) + n];
#pragma unroll
        for (int px = 0; px < 4; px++) {
            int lab = i4get(lab4, px);
            unsigned long long pr[4];
#pragma unroll
            for (int k = 0; k < 4; k++)
                pr[k] = pack2(f4get(v[2 * k], px), f4get(v[2 * k + 1], px));
#pragma unroll
            for (int c = 0; c < CC; c++) {
                bool hit = (lab == c);
                unsigned long long m2 = hit ? ONE2 : 0ull;
                icnt[c] += hit;
#pragma unroll
                for (int k = 0; k < 4; k++) acc[c][k] = ffma2(m2, pr[k], acc[c][k]);
            }
        }
    }

    // warp tree-reduce (packed adds)
#pragma unroll
    for (int c = 0; c < CC; c++) {
#pragma unroll
        for (int k = 0; k < 4; k++) {
            unsigned long long x = acc[c][k];
#pragma unroll
            for (int o = 16; o > 0; o >>= 1)
                x = fadd2(x, __shfl_down_sync(0xffffffffu, x, o));
            acc[c][k] = x;
        }
        int ic = icnt[c];
#pragma unroll
        for (int o = 16; o > 0; o >>= 1) ic += __shfl_down_sync(0xffffffffu, ic, o);
        icnt[c] = ic;
    }

    __shared__ float sw[4][72];
    int wid = tid >> 5, lane = tid & 31;
    if (lane == 0) {
#pragma unroll
        for (int c = 0; c < CC; c++) {
#pragma unroll
            for (int k = 0; k < 4; k++) {
                float lo, hi;
                unpack2(acc[c][k], lo, hi);
                sw[wid][c * NF + 2 * k]     = lo;
                sw[wid][c * NF + 2 * k + 1] = hi;
            }
            sw[wid][64 + c] = (float)icnt[c];
        }
    }
    __syncthreads();
    if (tid < 72) {
        float s = sw[0][tid] + sw[1][tid] + sw[2][tid] + sw[3][tid];
        if (tid < 64)
            atomicAdd(&((float*)g_s.sums)[b * 64 + tid], s);
        else
            atomicAdd(&g_s.counts[b][tid - 64], s);
        __threadfence();
    }
    __syncthreads();

    // ---------------- Grid-wide barrier ------------------------------------
    if (tid == 0) {
        unsigned int a = atomicAdd(&g_s.arrive, 1u);
        if (a == TOTAL_BLOCKS - 1) {
            atomicExch(&g_s.release, 1u);
        } else {
            volatile unsigned int* rel = &g_s.release;
            while (*rel == 0u) { __nanosleep(64); }
        }
    }
    __syncthreads();
    __threadfence();  // acquire: make all blocks' sums/counts visible

    // ---------------- Phase B: hinge distance to own-cluster mean ----------
    __shared__ float smean[NF][CC];
    if (tid < 64) {
        int c = tid & 7, f = tid >> 3;
        smean[f][c] = g_s.sums[b][c][f] / g_s.counts[b][c];
    }
    __syncthreads();

    float local = 0.f;
    for (int n = blockIdx.x * blockDim.x + tid; n < NG;
         n += BLKX * blockDim.x) {
        int4 lab4 = g[n];
        float4 v[NF];
#pragma unroll
        for (int f = 0; f < NF; f++) v[f] = p[f * (NPIX / 4) + n];
#pragma unroll
        for (int px = 0; px < 4; px++) {
            int lab = i4get(lab4, px);
            float d2 = 0.f;
#pragma unroll
            for (int f = 0; f < NF; f++) {
                float d = smean[f][lab] - f4get(v[f], px);
                d2 = fmaf(d, d, d2);
            }
            float t = sqrtf(d2) - 0.5f;  // DELTA_V
            t = fminf(fmaxf(t, 0.f), 100000.f);
            local = fmaf(t, t, local);
        }
    }

#pragma unroll
    for (int o = 16; o > 0; o >>= 1)
        local += __shfl_down_sync(0xffffffffu, local, o);
    __shared__ float sred[4];
    if (lane == 0) sred[wid] = local;
    __syncthreads();
    if (tid == 0) {
        float s = sred[0] + sred[1] + sred[2] + sred[3];
        atomicAdd(&g_s.dist[b], s);
    }

    // ---------------- Last-block finalize ----------------------------------
    __shared__ bool s_last;
    __threadfence();
    if (tid == 0) {
        unsigned int t = atomicAdd(&g_s.ticket, 1u);
        s_last = (t == TOTAL_BLOCKS - 1);
    }
    __syncthreads();
    if (!s_last) return;

    // 128 threads: tid = b*32 + i*... need B*C*C = 256 slots -> 2 per thread
    __shared__ float smu[BN][CC][NF];
    __shared__ float s_ldist[BN], s_lreg[BN], s_inv[BN];
    {
        int t2 = tid;                 // covers (b0,b1) x c x f with two halves
        int bb = t2 >> 6, i = (t2 >> 3) & 7, j = t2 & 7;
        smu[bb][i][j]     = g_s.sums[bb][i][j] / g_s.counts[bb][i];
        smu[bb + 2][i][j] = g_s.sums[bb + 2][i][j] / g_s.counts[bb + 2][i];
    }
    if (tid < BN) { s_ldist[tid] = 0.f; s_lreg[tid] = 0.f; s_inv[tid] = 0.f; }
    __syncthreads();

#pragma unroll
    for (int half = 0; half < 2; half++) {
        int t2 = tid + half * 128;
        int bb = t2 >> 6, i = (t2 >> 3) & 7, j = t2 & 7;
        if (i != j) {
            float d2 = 0.f;
#pragma unroll
            for (int f = 0; f < NF; f++) {
                float d = smu[bb][i][f] - smu[bb][j][f];
                d2 = fmaf(d, d, d2);
            }
            float t = 3.0f - sqrtf(d2);  // 2 * DELTA_D
            t = fminf(fmaxf(t, 0.f), 100000.f);
            atomicAdd(&s_ldist[bb], t * t);
        } else {
            float d2 = 0.f;
#pragma unroll
            for (int f = 0; f < NF; f++)
                d2 = fmaf(smu[bb][i][f], smu[bb][i][f], d2);
            atomicAdd(&s_lreg[bb], sqrtf(d2));
            atomicAdd(&s_inv[bb], 1.0f / g_s.counts[bb][i]);
        }
    }
    __syncthreads();

    if (tid == 0) {
        float total = 0.f;
#pragma unroll
        for (int q = 0; q < BN; q++) {
            float dq = __ldcg(&g_s.dist[q]);
            float l_var  = dq * s_inv[q] / (float)CC;
            float l_dist = s_ldist[q] / (float)(CC * (CC - 1));
            float l_reg  = s_lreg[q] / (float)CC;
            total += l_var + l_dist + 0.001f * l_reg;
        }
        out[0] = total / (float)BN;
    }
}

extern "C" void kernel_launch(void* const* d_in, const int* in_sizes, int n_in,
                              void* d_out, int out_size) {
    const float* pred = (const float*)d_in[0];
    const int*   tgt  = (const int*)d_in[1];
    float*       out  = (float*)d_out;
    (void)in_sizes; (void)n_in; (void)out_size;

    void* scratch_ptr = nullptr;
    cudaGetSymbolAddress(&scratch_ptr, g_s);
    cudaMemsetAsync(scratch_ptr, 0, sizeof(Scratch));

    dim3 grid(BLKX, BN);
    k_fused<<<grid, 128>>>(pred, tgt, out);
}

// round 4
// speedup vs baseline: 1.1475x; 1.1475x over previous
#include <cuda_runtime.h>
#include <cuda_fp16.h>

#define BN   4
#define NF   8
#define CC   8
#define NPIX (512 * 512)
#define NG   (NPIX / 4)          // 65536 pixel-groups per image
#define BPI  37                  // blocks per image
#define NBLK (BN * BPI)          // 148 = one block per SM
#define NGB  ((NG + BPI - 1) / BPI)  // 1772 groups per block
#define NTHR 512

#define SMEM_PRED_BYTES (NGB * 4 * 16)              // 113408: uint4 per pixel
#define SMEM_TOTAL      (SMEM_PRED_BYTES + NGB * 4) // + packed labels

struct Scratch {
    float sums[BN][CC][NF];
    float counts[BN][CC];
    float dist[BN];
    unsigned int arrive;
    unsigned int release;
    unsigned int ticket;
};
__device__ Scratch g_s;

__device__ __forceinline__ unsigned long long ffma2(unsigned long long a,
                                                    unsigned long long b,
                                                    unsigned long long c) {
    unsigned long long d;
    asm("fma.rn.f32x2 %0, %1, %2, %3;" : "=l"(d) : "l"(a), "l"(b), "l"(c));
    return d;
}
__device__ __forceinline__ unsigned long long fadd2(unsigned long long a,
                                                    unsigned long long b) {
    unsigned long long d;
    asm("add.rn.f32x2 %0, %1, %2;" : "=l"(d) : "l"(a), "l"(b));
    return d;
}
__device__ __forceinline__ unsigned long long pack2(float lo, float hi) {
    unsigned long long r;
    asm("mov.b64 %0, {%1, %2};" : "=l"(r) : "f"(lo), "f"(hi));
    return r;
}
__device__ __forceinline__ void unpack2(unsigned long long v, float& lo, float& hi) {
    asm("mov.b64 {%0, %1}, %2;" : "=f"(lo), "=f"(hi) : "l"(v));
}
__device__ __forceinline__ float f4get(const float4 v, int i) {
    return i == 0 ? v.x : i == 1 ? v.y : i == 2 ? v.z : v.w;
}
__device__ __forceinline__ int i4get(const int4 v, int i) {
    return i == 0 ? v.x : i == 1 ? v.y : i == 2 ? v.z : v.w;
}
__device__ __forceinline__ unsigned h2u(__half2 h) {
    return *reinterpret_cast<unsigned*>(&h);
}
__device__ __forceinline__ float2 u2f2(unsigned u) {
    return __half22float2(*reinterpret_cast<__half2*>(&u));
}

__global__ void __launch_bounds__(NTHR, 1)
k_all(const float* __restrict__ pred, const int* __restrict__ tgt,
      float* __restrict__ out) {
    extern __shared__ unsigned char smem_raw[];
    uint4*    spred = (uint4*)smem_raw;                          // [NGB*4]
    unsigned* slab  = (unsigned*)(smem_raw + SMEM_PRED_BYTES);   // [NGB]

    const int tid = threadIdx.x;
    const int bx  = blockIdx.x;
    const int img = bx / BPI;
    const int li  = bx % BPI;
    const int g0  = li * NGB;
    const int g1  = (g0 + NGB < NG) ? g0 + NGB : NG;

    const float4* p = (const float4*)(pred + (size_t)img * NF * NPIX);
    const int4*   g = (const int4*)(tgt + (size_t)img * NPIX);
    const unsigned long long ONE2 = 0x3F8000003F800000ull;

    // ================= Phase A: load once, accumulate, cache to smem =======
    unsigned long long acc[CC][4];
    int icnt[CC];
#pragma unroll
    for (int c = 0; c < CC; c++) {
        icnt[c] = 0;
#pragma unroll
        for (int k = 0; k < 4; k++) acc[c][k] = 0ull;
    }

    for (int n = g0 + tid; n < g1; n += NTHR) {
        int4 lab4 = g[n];
        float4 v[NF];
#pragma unroll
        for (int f = 0; f < NF; f++) v[f] = p[f * NG + n];

        int gl = n - g0;
        slab[gl] = (unsigned)(lab4.x) | ((unsigned)(lab4.y) << 8) |
                   ((unsigned)(lab4.z) << 16) | ((unsigned)(lab4.w) << 24);

#pragma unroll
        for (int px = 0; px < 4; px++) {
            int lab = i4get(lab4, px);
            unsigned long long pr[4];
            uint4 hq;
            {
                float a0 = f4get(v[0], px), a1 = f4get(v[1], px);
                float a2 = f4get(v[2], px), a3 = f4get(v[3], px);
                float a4 = f4get(v[4], px), a5 = f4get(v[5], px);
                float a6 = f4get(v[6], px), a7 = f4get(v[7], px);
                pr[0] = pack2(a0, a1); pr[1] = pack2(a2, a3);
                pr[2] = pack2(a4, a5); pr[3] = pack2(a6, a7);
                hq.x = h2u(__floats2half2_rn(a0, a1));
                hq.y = h2u(__floats2half2_rn(a2, a3));
                hq.z = h2u(__floats2half2_rn(a4, a5));
                hq.w = h2u(__floats2half2_rn(a6, a7));
            }
            spred[gl * 4 + px] = hq;
#pragma unroll
            for (int c = 0; c < CC; c++) {
                bool hit = (lab == c);
                unsigned long long m2 = hit ? ONE2 : 0ull;
                icnt[c] += hit;
#pragma unroll
                for (int k = 0; k < 4; k++) acc[c][k] = ffma2(m2, pr[k], acc[c][k]);
            }
        }
    }

    // warp tree-reduce, then cross-warp via (static) shared
#pragma unroll
    for (int c = 0; c < CC; c++) {
#pragma unroll
        for (int k = 0; k < 4; k++) {
            unsigned long long x = acc[c][k];
#pragma unroll
            for (int o = 16; o > 0; o >>= 1)
                x = fadd2(x, __shfl_down_sync(0xffffffffu, x, o));
            acc[c][k] = x;
        }
        int ic = icnt[c];
#pragma unroll
        for (int o = 16; o > 0; o >>= 1) ic += __shfl_down_sync(0xffffffffu, ic, o);
        icnt[c] = ic;
    }

    __shared__ float sw[16][72];   // 16 warps x (64 sums + 8 counts)
    int wid = tid >> 5, lane = tid & 31;
    if (lane == 0) {
#pragma unroll
        for (int c = 0; c < CC; c++) {
#pragma unroll
            for (int k = 0; k < 4; k++) {
                float lo, hi;
                unpack2(acc[c][k], lo, hi);
                sw[wid][c * NF + 2 * k]     = lo;
                sw[wid][c * NF + 2 * k + 1] = hi;
            }
            sw[wid][64 + c] = (float)icnt[c];
        }
    }
    __syncthreads();
    if (tid < 72) {
        float s = 0.f;
#pragma unroll
        for (int w = 0; w < 16; w++) s += sw[w][tid];
        if (tid < 64)
            atomicAdd(&((float*)g_s.sums)[img * 64 + tid], s);
        else
            atomicAdd(&g_s.counts[img][tid - 64], s);
    }
    __threadfence();
    __syncthreads();

    // ================= Grid barrier (148 resident blocks) ==================
    if (tid == 0) {
        unsigned int a = atomicAdd(&g_s.arrive, 1u);
        if (a == NBLK - 1) {
            atomicExch(&g_s.release, 1u);
        } else {
            volatile unsigned int* rel = &g_s.release;
            while (*rel == 0u) { __nanosleep(64); }
        }
    }
    __syncthreads();
    __threadfence();

    // ================= Phase B: hinge distance from smem-cached pred =======
    __shared__ float smean[NF][CC];
    if (tid < 64) {
        int c = tid & 7, f = tid >> 3;
        smean[f][c] = __ldcg(&g_s.sums[img][c][f]) / __ldcg(&g_s.counts[img][c]);
    }
    __syncthreads();

    float local = 0.f;
    for (int n = g0 + tid; n < g1; n += NTHR) {
        int gl = n - g0;
        unsigned lw = slab[gl];
#pragma unroll
        for (int px = 0; px < 4; px++) {
            uint4 hq = spred[gl * 4 + px];
            int lab = (lw >> (8 * px)) & 0xFF;
            float2 a01 = u2f2(hq.x), a23 = u2f2(hq.y);
            float2 a45 = u2f2(hq.z), a67 = u2f2(hq.w);
            float d2 = 0.f, d;
            d = smean[0][lab] - a01.x; d2 = fmaf(d, d, d2);
            d = smean[1][lab] - a01.y; d2 = fmaf(d, d, d2);
            d = smean[2][lab] - a23.x; d2 = fmaf(d, d, d2);
            d = smean[3][lab] - a23.y; d2 = fmaf(d, d, d2);
            d = smean[4][lab] - a45.x; d2 = fmaf(d, d, d2);
            d = smean[5][lab] - a45.y; d2 = fmaf(d, d, d2);
            d = smean[6][lab] - a67.x; d2 = fmaf(d, d, d2);
            d = smean[7][lab] - a67.y; d2 = fmaf(d, d, d2);
            float t = sqrtf(d2) - 0.5f;          // DELTA_V
            t = fminf(fmaxf(t, 0.f), 100000.f);
            local = fmaf(t, t, local);
        }
    }

#pragma unroll
    for (int o = 16; o > 0; o >>= 1)
        local += __shfl_down_sync(0xffffffffu, local, o);
    __shared__ float sred[16];
    if (lane == 0) sred[wid] = local;
    __syncthreads();
    if (tid == 0) {
        float s = 0.f;
#pragma unroll
        for (int w = 0; w < 16; w++) s += sred[w];
        atomicAdd(&g_s.dist[img], s);
    }

    // ================= Last-block finalize =================================
    __shared__ bool s_last;
    __threadfence();
    if (tid == 0) {
        unsigned int t = atomicAdd(&g_s.ticket, 1u);
        s_last = (t == NBLK - 1);
    }
    __syncthreads();
    if (!s_last) return;

    __shared__ float smu[BN][CC][NF];
    __shared__ float s_ldist[BN], s_lreg[BN], s_inv[BN];
    if (tid < 256) {
        int bb = tid >> 6, i = (tid >> 3) & 7, j = tid & 7;
        smu[bb][i][j] = __ldcg(&g_s.sums[bb][i][j]) / __ldcg(&g_s.counts[bb][i]);
    }
    if (tid < BN) { s_ldist[tid] = 0.f; s_lreg[tid] = 0.f; s_inv[tid] = 0.f; }
    __syncthreads();

    if (tid < 256) {
        int bb = tid >> 6, i = (tid >> 3) & 7, j = tid & 7;
        if (i != j) {
            float d2 = 0.f;
#pragma unroll
            for (int f = 0; f < NF; f++) {
                float d = smu[bb][i][f] - smu[bb][j][f];
                d2 = fmaf(d, d, d2);
            }
            float t = 3.0f - sqrtf(d2);          // 2 * DELTA_D
            t = fminf(fmaxf(t, 0.f), 100000.f);
            atomicAdd(&s_ldist[bb], t * t);
        } else {
            float d2 = 0.f;
#pragma unroll
            for (int f = 0; f < NF; f++)
                d2 = fmaf(smu[bb][i][f], smu[bb][i][f], d2);
            atomicAdd(&s_lreg[bb], sqrtf(d2));
            atomicAdd(&s_inv[bb], 1.0f / __ldcg(&g_s.counts[bb][i]));
        }
    }
    __syncthreads();

    if (tid == 0) {
        float total = 0.f;
#pragma unroll
        for (int q = 0; q < BN; q++) {
            float dq = __ldcg(&g_s.dist[q]);
            float l_var  = dq * s_inv[q] / (float)CC;
            float l_dist = s_ldist[q] / (float)(CC * (CC - 1));
            float l_reg  = s_lreg[q] / (float)CC;
            total += l_var + l_dist + 0.001f * l_reg;
        }
        out[0] = total / (float)BN;
    }
}

extern "C" void kernel_launch(void* const* d_in, const int* in_sizes, int n_in,
                              void* d_out, int out_size) {
    const float* pred = (const float*)d_in[0];
    const int*   tgt  = (const int*)d_in[1];
    float*       out  = (float*)d_out;
    (void)in_sizes; (void)n_in; (void)out_size;

    static bool attr_done = false;
    if (!attr_done) {
        cudaFuncSetAttribute(k_all, cudaFuncAttributeMaxDynamicSharedMemorySize,
                             SMEM_TOTAL);
        attr_done = true;
    }

    void* scratch_ptr = nullptr;
    cudaGetSymbolAddress(&scratch_ptr, g_s);
    cudaMemsetAsync(scratch_ptr, 0, sizeof(Scratch));

    k_all<<<NBLK, NTHR, SMEM_TOTAL>>>(pred, tgt, out);
}